// round 12
// baseline (speedup 1.0000x reference)
#include <cuda_runtime.h>
#include <math.h>
#include <stdint.h>

// Problem constants
#define NB  2
#define NL  2048
#define ND  1024
#define NH  8
#define NHD 128
#define NZ  (NB*NH)   // 16 batched heads

// ---------------- static device scratch ----------------
__device__ float g_Q[(size_t)NZ * NL * NHD];   // [z][l][j]
__device__ float g_K[(size_t)NZ * NL * NHD];   // [z][l][j]
__device__ float g_V[(size_t)NZ * NHD * NL];   // transposed: [z][j][l]
__device__ float g_S[(size_t)NZ * NL * NL];    // scores/probs
__device__ float g_A[(size_t)NB * NL * ND];    // concat attention output
__device__ float g_R[(size_t)NB * NL * ND];    // pre-LN result
__device__ float g_WT[(size_t)4 * ND * ND];    // transposed weights: [q,k,v,o][out][in]
__device__ int   g_mask_flag;                  // 0=int32, 1=byte, 2=float32

// ---------------- tf32 helpers (sm_80+ PTX; legal under compute_103) ----------------
__device__ __forceinline__ uint32_t cvt_tf32(float x) {
    uint32_t u; asm("cvt.rna.tf32.f32 %0, %1;" : "=r"(u) : "f"(x)); return u;
}
__device__ __forceinline__ void mma_tf32(float* d, const uint32_t* a, const uint32_t* b) {
    asm volatile(
        "mma.sync.aligned.m16n8k8.row.col.f32.tf32.tf32.f32 "
        "{%0,%1,%2,%3}, {%4,%5,%6,%7}, {%8,%9}, {%0,%1,%2,%3};"
        : "+f"(d[0]), "+f"(d[1]), "+f"(d[2]), "+f"(d[3])
        : "r"(a[0]), "r"(a[1]), "r"(a[2]), "r"(a[3]), "r"(b[0]), "r"(b[1]));
}

// ---------------- shared GEMM core: 128x128 CTA tile, BK=16, 256 thr ----------------
// A: [128 rows][K] row-major (lda). B: [128 rows][K] row-major (ldb) = op-B^T (row.col).
// Warp layout: 8 warps as 4(M) x 2(N); warp tile 32x64; per warp 2x8 m16n8k8 tiles.
// Smem rows padded to 20 floats: (row*20 + col) mod 32 is a perfect bank permutation
// for the 8-row x 4-col fragment access pattern (conflict-free), 80B rows stay 16B-aligned.
#define LDR 20

__device__ __forceinline__ void gemm_mma(
    const float* __restrict__ A, int lda,
    const float* __restrict__ B, int ldb,
    int K, float acc[2][8][4])
{
    __shared__ float sA[128 * LDR];
    __shared__ float sB[128 * LDR];
    const uint32_t* sAu = (const uint32_t*)sA;
    const uint32_t* sBu = (const uint32_t*)sB;

    const int tid  = threadIdx.x;
    const int lane = tid & 31, wid = tid >> 5;
    const int wm = wid & 3, wn = wid >> 2;
    const int gid = lane >> 2, tq = lane & 3;
    const int m0 = wm * 32, n0 = wn * 64;

    // staging: each thread moves 2 float4 chunks of A and 2 of B per BK=16 tile
    const int r0 = tid >> 2;               // rows 0..63
    const int r1 = r0 + 64;                // rows 64..127
    const int kq = (tid & 3) << 2;         // float offset within 16-wide k slab

    #pragma unroll
    for (int mi = 0; mi < 2; mi++)
        #pragma unroll
        for (int ni = 0; ni < 8; ni++)
            #pragma unroll
            for (int r = 0; r < 4; r++) acc[mi][ni][r] = 0.0f;

    float4 av0, av1, bv0, bv1;
    av0 = *(const float4*)(A + (size_t)r0 * lda + kq);
    av1 = *(const float4*)(A + (size_t)r1 * lda + kq);
    bv0 = *(const float4*)(B + (size_t)r0 * ldb + kq);
    bv1 = *(const float4*)(B + (size_t)r1 * ldb + kq);

    const int T = K >> 4;
    for (int t = 0; t < T; t++) {
        // convert to tf32 (RNE) and stage
        uint4 u;
        u.x = cvt_tf32(av0.x); u.y = cvt_tf32(av0.y); u.z = cvt_tf32(av0.z); u.w = cvt_tf32(av0.w);
        *(uint4*)&sA[r0 * LDR + kq] = u;
        u.x = cvt_tf32(av1.x); u.y = cvt_tf32(av1.y); u.z = cvt_tf32(av1.z); u.w = cvt_tf32(av1.w);
        *(uint4*)&sA[r1 * LDR + kq] = u;
        u.x = cvt_tf32(bv0.x); u.y = cvt_tf32(bv0.y); u.z = cvt_tf32(bv0.z); u.w = cvt_tf32(bv0.w);
        *(uint4*)&sB[r0 * LDR + kq] = u;
        u.x = cvt_tf32(bv1.x); u.y = cvt_tf32(bv1.y); u.z = cvt_tf32(bv1.z); u.w = cvt_tf32(bv1.w);
        *(uint4*)&sB[r1 * LDR + kq] = u;
        __syncthreads();

        if (t + 1 < T) {                    // prefetch next tile into registers
            const float* An = A + (t + 1) * 16;
            const float* Bn = B + (t + 1) * 16;
            av0 = *(const float4*)(An + (size_t)r0 * lda + kq);
            av1 = *(const float4*)(An + (size_t)r1 * lda + kq);
            bv0 = *(const float4*)(Bn + (size_t)r0 * ldb + kq);
            bv1 = *(const float4*)(Bn + (size_t)r1 * ldb + kq);
        }

        #pragma unroll
        for (int ks = 0; ks < 16; ks += 8) {
            uint32_t af[2][4], bf[8][2];
            #pragma unroll
            for (int mi = 0; mi < 2; mi++) {
                int mr = m0 + mi * 16 + gid;
                af[mi][0] = sAu[mr * LDR + ks + tq];
                af[mi][1] = sAu[(mr + 8) * LDR + ks + tq];
                af[mi][2] = sAu[mr * LDR + ks + tq + 4];
                af[mi][3] = sAu[(mr + 8) * LDR + ks + tq + 4];
            }
            #pragma unroll
            for (int ni = 0; ni < 8; ni++) {
                int nr = n0 + ni * 8 + gid;
                bf[ni][0] = sBu[nr * LDR + ks + tq];
                bf[ni][1] = sBu[nr * LDR + ks + tq + 4];
            }
            #pragma unroll
            for (int mi = 0; mi < 2; mi++)
                #pragma unroll
                for (int ni = 0; ni < 8; ni++)
                    mma_tf32(acc[mi][ni], af[mi], bf[ni]);
        }
        __syncthreads();
    }
}

// epilogue index helpers (element (mi, ni, half hh, e): rows/cols in CTA tile)
// row = m0 + mi*16 + gid + hh*8 ; col = n0 + ni*8 + tq*2 + e ; val = acc[mi][ni][hh*2+e]

// ---------------- mask dtype detection ----------------
__global__ void k_detect(const unsigned char* __restrict__ m) {
    __shared__ int f1, f3;
    if (threadIdx.x == 0) { f1 = 0; f3 = 0; }
    __syncthreads();
    int l1 = 0, l3 = 0;
    const uchar4* m4 = reinterpret_cast<const uchar4*>(m);
    for (int i = threadIdx.x; i < 16384; i += 256) { uchar4 c = m4[i]; l1 |= c.y; l3 |= c.w; }
    if (l1) atomicOr(&f1, 1);
    if (l3) atomicOr(&f3, 1);
    __syncthreads();
    if (threadIdx.x == 0) g_mask_flag = f1 ? 1 : (f3 ? 2 : 0);
}

// ---------------- weight transpose: g_WT[z][out][in] = W[in][out] ----------------
__global__ void k_transp(const float* __restrict__ W0, const float* __restrict__ W1,
                         const float* __restrict__ W2, const float* __restrict__ W3) {
    __shared__ float t[32][33];
    const int z = blockIdx.z;
    const float* W = (z == 0) ? W0 : (z == 1) ? W1 : (z == 2) ? W2 : W3;
    float* O = g_WT + (size_t)z * ND * ND;
    int x = blockIdx.x * 32 + threadIdx.x;
    #pragma unroll
    for (int j = 0; j < 32; j += 8)
        t[threadIdx.y + j][threadIdx.x] = W[(size_t)(blockIdx.y * 32 + threadIdx.y + j) * ND + x];
    __syncthreads();
    int ox = blockIdx.y * 32 + threadIdx.x;
    #pragma unroll
    for (int j = 0; j < 32; j += 8)
        O[(size_t)(blockIdx.x * 32 + threadIdx.y + j) * ND + ox] = t[threadIdx.x][threadIdx.y + j];
}

// ---------------- QKV projections, head-deinterleave epilogue ----------------
__global__ __launch_bounds__(256) void k_qkv_t(
    const float* __restrict__ de, const float* __restrict__ en,
    const float* __restrict__ bq, const float* __restrict__ bk, const float* __restrict__ bv) {
    const int z = blockIdx.z;
    const float* X    = (z == 0) ? de : en;
    const float* bias = (z == 0) ? bq : (z == 1 ? bk : bv);
    const float* WT   = g_WT + (size_t)z * ND * ND;
    const int bm = blockIdx.y * 128, bn = blockIdx.x * 128;

    float acc[2][8][4];
    gemm_mma(X + (size_t)bm * ND, ND, WT + (size_t)bn * ND, ND, ND, acc);

    const int lane = threadIdx.x & 31, wid = threadIdx.x >> 5;
    const int m0 = (wid & 3) * 32, n0 = (wid >> 2) * 64;
    const int gid = lane >> 2, tq = lane & 3;
    float* qdst = (z == 0) ? g_Q : g_K;
    #pragma unroll
    for (int mi = 0; mi < 2; mi++)
        #pragma unroll
        for (int hh = 0; hh < 2; hh++) {
            int m = bm + m0 + mi * 16 + gid + hh * 8;
            int b = m >> 11, l = m & (NL - 1);
            #pragma unroll
            for (int ni = 0; ni < 8; ni++)
                #pragma unroll
                for (int e = 0; e < 2; e++) {
                    int n = bn + n0 + ni * 8 + tq * 2 + e;
                    float val = acc[mi][ni][hh * 2 + e] + bias[n];
                    int h = n & 7, jj = n >> 3;    // interleaved split: feature = jj*8+h
                    if (z < 2) qdst[(((size_t)(b * NH + h) * NL + l) << 7) + jj] = val;
                    else       g_V[((size_t)(b * NH + h) * NHD + jj) * NL + l] = val;  // V^T
                }
        }
}

// ---------------- S = Q K^T / 32, masked ----------------
__global__ __launch_bounds__(256) void k_qk_t(const unsigned char* __restrict__ maskraw) {
    const int z = blockIdx.z, b = z >> 3;
    const int bm = blockIdx.y * 128, bn = blockIdx.x * 128;
    const float* Qb = g_Q + (size_t)z * NL * NHD;
    const float* Kb = g_K + (size_t)z * NL * NHD;

    float acc[2][8][4];
    gemm_mma(Qb + (size_t)bm * NHD, NHD, Kb + (size_t)bn * NHD, NHD, NHD, acc);

    const int lane = threadIdx.x & 31, wid = threadIdx.x >> 5;
    const int m0 = (wid & 3) * 32, n0 = (wid >> 2) * 64;
    const int gid = lane >> 2, tq = lane & 3;
    const int mf = g_mask_flag;
    #pragma unroll
    for (int mi = 0; mi < 2; mi++)
        #pragma unroll
        for (int hh = 0; hh < 2; hh++) {
            int m = bm + m0 + mi * 16 + gid + hh * 8;
            const size_t mrow = ((size_t)b * NL + m) * NL;
            float* srow = g_S + ((size_t)z * NL + m) * NL;
            #pragma unroll
            for (int ni = 0; ni < 8; ni++) {
                int n = bn + n0 + ni * 8 + tq * 2;
                float v0 = acc[mi][ni][hh * 2 + 0] * 0.03125f;   // 1/sqrt(1024)
                float v1 = acc[mi][ni][hh * 2 + 1] * 0.03125f;
                bool k0, k1;
                if (mf == 1) {
                    const unsigned char* mp = maskraw + mrow + n;
                    k0 = mp[0] != 0; k1 = mp[1] != 0;
                } else if (mf == 2) {
                    const float* mp = (const float*)maskraw + mrow + n;
                    k0 = mp[0] != 0.0f; k1 = mp[1] != 0.0f;
                } else {
                    const int* mp = (const int*)maskraw + mrow + n;
                    k0 = mp[0] != 0; k1 = mp[1] != 0;
                }
                float2 o;
                o.x = k0 ? -1e10f : v0;
                o.y = k1 ? -1e10f : v1;
                *(float2*)(srow + n) = o;
            }
        }
}

// ---------------- O = P V, concat-layout epilogue ----------------
__global__ __launch_bounds__(256) void k_pv_t() {
    const int z = blockIdx.z, b = z >> 3, h = z & 7;
    const int bm = blockIdx.y * 128;
    const float* P  = g_S + (size_t)z * NL * NL + (size_t)bm * NL;
    const float* Vt = g_V + (size_t)z * NHD * NL;        // [j][l], ld = NL

    float acc[2][8][4];
    gemm_mma(P, NL, Vt, NL, NL, acc);

    const int lane = threadIdx.x & 31, wid = threadIdx.x >> 5;
    const int m0 = (wid & 3) * 32, n0 = (wid >> 2) * 64;
    const int gid = lane >> 2, tq = lane & 3;
    #pragma unroll
    for (int mi = 0; mi < 2; mi++)
        #pragma unroll
        for (int hh = 0; hh < 2; hh++) {
            int m = bm + m0 + mi * 16 + gid + hh * 8;
            float* arow = g_A + ((size_t)b * NL + m) * ND + h * NHD;
            #pragma unroll
            for (int ni = 0; ni < 8; ni++) {
                int n = n0 + ni * 8 + tq * 2;
                float2 o;
                o.x = acc[mi][ni][hh * 2 + 0];
                o.y = acc[mi][ni][hh * 2 + 1];
                *(float2*)(arow + n) = o;
            }
        }
}

// ---------------- R = A Wo + bo + de (residual) ----------------
__global__ __launch_bounds__(256) void k_out_t(const float* __restrict__ bo,
                                               const float* __restrict__ de) {
    const int bm = blockIdx.y * 128, bn = blockIdx.x * 128;
    const float* WoT = g_WT + (size_t)3 * ND * ND;

    float acc[2][8][4];
    gemm_mma(g_A + (size_t)bm * ND, ND, WoT + (size_t)bn * ND, ND, ND, acc);

    const int lane = threadIdx.x & 31, wid = threadIdx.x >> 5;
    const int m0 = (wid & 3) * 32, n0 = (wid >> 2) * 64;
    const int gid = lane >> 2, tq = lane & 3;
    #pragma unroll
    for (int mi = 0; mi < 2; mi++)
        #pragma unroll
        for (int hh = 0; hh < 2; hh++) {
            int m = bm + m0 + mi * 16 + gid + hh * 8;
            const float* drow = de + (size_t)m * ND;
            float* rrow = g_R + (size_t)m * ND;
            #pragma unroll
            for (int ni = 0; ni < 8; ni++) {
                int n = bn + n0 + ni * 8 + tq * 2;
                float2 d2 = *(const float2*)(drow + n);
                float2 b2 = *(const float2*)(bo + n);
                float2 o;
                o.x = acc[mi][ni][hh * 2 + 0] + b2.x + d2.x;
                o.y = acc[mi][ni][hh * 2 + 1] + b2.y + d2.y;
                *(float2*)(rrow + n) = o;
            }
        }
}

// ---------------- block-wide allreduce ----------------
__device__ __forceinline__ float blockAllReduce(float v, bool doMax) {
    __shared__ float sh[8];
    __shared__ float res;
    #pragma unroll
    for (int o = 16; o; o >>= 1) {
        float t = __shfl_xor_sync(0xffffffffu, v, o);
        v = doMax ? fmaxf(v, t) : (v + t);
    }
    if ((threadIdx.x & 31) == 0) sh[threadIdx.x >> 5] = v;
    __syncthreads();
    if (threadIdx.x < 32) {
        float t = (threadIdx.x < 8) ? sh[threadIdx.x] : (doMax ? -INFINITY : 0.0f);
        #pragma unroll
        for (int o = 4; o; o >>= 1) {
            float u = __shfl_xor_sync(0xffffffffu, t, o);
            t = doMax ? fmaxf(t, u) : (t + u);
        }
        if (threadIdx.x == 0) res = t;
    }
    __syncthreads();
    return res;
}

// ---------------- row softmax over S (in place) ----------------
__global__ __launch_bounds__(256) void k_softmax() {
    size_t row = blockIdx.x;
    float4* p = reinterpret_cast<float4*>(g_S) + row * (NL / 4);
    float4 a = p[threadIdx.x];
    float4 c = p[threadIdx.x + 256];
    float m = fmaxf(fmaxf(fmaxf(a.x, a.y), fmaxf(a.z, a.w)),
                    fmaxf(fmaxf(c.x, c.y), fmaxf(c.z, c.w)));
    m = blockAllReduce(m, true);
    a.x = __expf(a.x - m); a.y = __expf(a.y - m); a.z = __expf(a.z - m); a.w = __expf(a.w - m);
    c.x = __expf(c.x - m); c.y = __expf(c.y - m); c.z = __expf(c.z - m); c.w = __expf(c.w - m);
    float s = a.x + a.y + a.z + a.w + c.x + c.y + c.z + c.w;
    s = blockAllReduce(s, false);
    float inv = 1.0f / s;
    a.x *= inv; a.y *= inv; a.z *= inv; a.w *= inv;
    c.x *= inv; c.y *= inv; c.z *= inv; c.w *= inv;
    p[threadIdx.x] = a;
    p[threadIdx.x + 256] = c;
}

// ---------------- LayerNorm (ddof=1, eps=1e-8, scalar gamma/beta) ----------------
__global__ __launch_bounds__(256) void k_ln(
    float* __restrict__ out, const float* __restrict__ gamma, const float* __restrict__ beta) {
    size_t row = blockIdx.x;
    const float4* x4 = reinterpret_cast<const float4*>(g_R) + row * (ND / 4);
    float4 v = x4[threadIdx.x];
    float s  = v.x + v.y + v.z + v.w;
    float ss = v.x * v.x + v.y * v.y + v.z * v.z + v.w * v.w;
    s  = blockAllReduce(s,  false);
    ss = blockAllReduce(ss, false);
    float mu  = s * (1.0f / 1024.0f);
    float var = (ss - 1024.0f * mu * mu) * (1.0f / 1023.0f);
    float w = rsqrtf(var + 1e-8f);
    float g = gamma[0] * w, bb = beta[0];
    float4 o;
    o.x = (v.x - mu) * g + bb;
    o.y = (v.y - mu) * g + bb;
    o.z = (v.z - mu) * g + bb;
    o.w = (v.w - mu) * g + bb;
    reinterpret_cast<float4*>(out)[row * (ND / 4) + threadIdx.x] = o;
}

// ---------------- launch ----------------
extern "C" void kernel_launch(void* const* d_in, const int* in_sizes, int n_in,
                              void* d_out, int out_size) {
    (void)in_sizes; (void)n_in; (void)out_size;
    const float* en = (const float*)d_in[0];
    const float* de = (const float*)d_in[1];
    const unsigned char* mask = (const unsigned char*)d_in[2];
    const float* Wq = (const float*)d_in[3];
    const float* bq = (const float*)d_in[4];
    const float* Wk = (const float*)d_in[5];
    const float* bk = (const float*)d_in[6];
    const float* Wv = (const float*)d_in[7];
    const float* bv = (const float*)d_in[8];
    const float* Wo = (const float*)d_in[9];
    const float* bo = (const float*)d_in[10];
    const float* gamma = (const float*)d_in[11];
    const float* beta  = (const float*)d_in[12];
    float* out = (float*)d_out;

    k_detect<<<1, 256>>>(mask);
    k_transp<<<dim3(32, 32, 4), dim3(32, 8)>>>(Wq, Wk, Wv, Wo);
    k_qkv_t<<<dim3(ND / 128, (NB * NL) / 128, 3), 256>>>(de, en, bq, bk, bv);
    k_qk_t<<<dim3(NL / 128, NL / 128, NZ), 256>>>(mask);
    k_softmax<<<NZ * NL, 256>>>();
    k_pv_t<<<dim3(1, NL / 128, NZ), 256>>>();
    k_out_t<<<dim3(ND / 128, (NB * NL) / 128, 1), 256>>>(bo, de);
    k_ln<<<NB * NL, 256>>>(out, gamma, beta);
}

// round 13
// speedup vs baseline: 1.1095x; 1.1095x over previous
#include <cuda_runtime.h>
#include <math.h>
#include <stdint.h>

// Problem constants
#define NB  2
#define NL  2048
#define ND  1024
#define NH  8
#define NHD 128
#define NZ  (NB*NH)   // 16 batched heads

// ---------------- static device scratch ----------------
__device__ float g_Q[(size_t)NZ * NL * NHD];   // [z][l][j]
__device__ float g_K[(size_t)NZ * NL * NHD];   // [z][l][j]
__device__ float g_V[(size_t)NZ * NHD * NL];   // transposed: [z][j][l]
__device__ float g_S[(size_t)NZ * NL * NL];    // scores/probs
__device__ float g_A[(size_t)NB * NL * ND];    // concat attention output
__device__ float g_R[(size_t)NB * NL * ND];    // pre-LN result
__device__ float g_WT[(size_t)4 * ND * ND];    // transposed weights: [q,k,v,o][out][in]
__device__ int   g_mask_flag;                  // 0=int32, 1=byte, 2=float32

// ---------------- tf32 helpers (sm_80+ PTX; legal under compute_103) ----------------
__device__ __forceinline__ uint32_t cvt_tf32(float x) {
    uint32_t u; asm("cvt.rna.tf32.f32 %0, %1;" : "=r"(u) : "f"(x)); return u;
}
__device__ __forceinline__ void mma_tf32(float* d, const uint32_t* a, const uint32_t* b) {
    asm volatile(
        "mma.sync.aligned.m16n8k8.row.col.f32.tf32.tf32.f32 "
        "{%0,%1,%2,%3}, {%4,%5,%6,%7}, {%8,%9}, {%0,%1,%2,%3};"
        : "+f"(d[0]), "+f"(d[1]), "+f"(d[2]), "+f"(d[3])
        : "r"(a[0]), "r"(a[1]), "r"(a[2]), "r"(a[3]), "r"(b[0]), "r"(b[1]));
}

// ---------------- shared GEMM core v2 ----------------
// CTA tile 128x128, BK=16, 128 threads = 4 warps as 2(M) x 2(N); warp tile 64x64.
// FLOP/smem-byte = 16 (vs 10.7 for 32x64) -> crossbar no longer the hard wall.
// Double-buffered smem: staging of tile t+1 overlaps MMAs of tile t, 1 sync/tile.
// Smem rows padded to LDR=20 floats: (row*20+col) mod 32 is a conflict-free bank
// permutation for the 8-row x 4-col fragment pattern; 80B rows keep 16B alignment.
#define LDR 20

__device__ __forceinline__ void gemm_mma(
    const float* __restrict__ A, int lda,
    const float* __restrict__ B, int ldb,
    int K, float acc[4][8][4])
{
    __shared__ float sA[2][128 * LDR];
    __shared__ float sB[2][128 * LDR];

    const int tid  = threadIdx.x;
    const int lane = tid & 31, wid = tid >> 5;
    const int wm = wid & 1, wn = wid >> 1;
    const int gid = lane >> 2, tq = lane & 3;
    const int m0 = wm * 64, n0 = wn * 64;

    const int r0 = tid >> 2;               // rows 0..31 (+32,+64,+96)
    const int kq = (tid & 3) << 2;          // float offset within 16-wide k slab

    #pragma unroll
    for (int mt = 0; mt < 4; mt++)
        #pragma unroll
        for (int nt = 0; nt < 8; nt++)
            #pragma unroll
            for (int r = 0; r < 4; r++) acc[mt][nt][r] = 0.0f;

    float4 av[4], bv[4];
    #pragma unroll
    for (int i = 0; i < 4; i++) {
        av[i] = *(const float4*)(A + (size_t)(r0 + 32 * i) * lda + kq);
        bv[i] = *(const float4*)(B + (size_t)(r0 + 32 * i) * ldb + kq);
    }
    #pragma unroll
    for (int i = 0; i < 4; i++) {           // stage tile 0 into buffer 0
        uint4 u;
        u.x = cvt_tf32(av[i].x); u.y = cvt_tf32(av[i].y); u.z = cvt_tf32(av[i].z); u.w = cvt_tf32(av[i].w);
        *(uint4*)&sA[0][(r0 + 32 * i) * LDR + kq] = u;
        u.x = cvt_tf32(bv[i].x); u.y = cvt_tf32(bv[i].y); u.z = cvt_tf32(bv[i].z); u.w = cvt_tf32(bv[i].w);
        *(uint4*)&sB[0][(r0 + 32 * i) * LDR + kq] = u;
    }
    __syncthreads();

    const int T = K >> 4;
    for (int t = 0; t < T; t++) {
        const int cur = t & 1;
        const uint32_t* sAu = (const uint32_t*)sA[cur];
        const uint32_t* sBu = (const uint32_t*)sB[cur];

        if (t + 1 < T) {                    // global prefetch for next tile
            const float* An = A + (t + 1) * 16;
            const float* Bn = B + (t + 1) * 16;
            #pragma unroll
            for (int i = 0; i < 4; i++) {
                av[i] = *(const float4*)(An + (size_t)(r0 + 32 * i) * lda + kq);
                bv[i] = *(const float4*)(Bn + (size_t)(r0 + 32 * i) * ldb + kq);
            }
        }

        #pragma unroll
        for (int ks = 0; ks < 16; ks += 8) {
            uint32_t af[4][4], bf[8][2];
            #pragma unroll
            for (int mt = 0; mt < 4; mt++) {
                int mr = m0 + mt * 16 + gid;
                af[mt][0] = sAu[mr * LDR + ks + tq];
                af[mt][1] = sAu[(mr + 8) * LDR + ks + tq];
                af[mt][2] = sAu[mr * LDR + ks + tq + 4];
                af[mt][3] = sAu[(mr + 8) * LDR + ks + tq + 4];
            }
            #pragma unroll
            for (int nt = 0; nt < 8; nt++) {
                int nr = n0 + nt * 8 + gid;
                bf[nt][0] = sBu[nr * LDR + ks + tq];
                bf[nt][1] = sBu[nr * LDR + ks + tq + 4];
            }
            #pragma unroll
            for (int mt = 0; mt < 4; mt++)
                #pragma unroll
                for (int nt = 0; nt < 8; nt++)
                    mma_tf32(acc[mt][nt], af[mt], bf[nt]);
        }

        if (t + 1 < T) {                    // stage next tile into the other buffer
            const int nxt = cur ^ 1;
            #pragma unroll
            for (int i = 0; i < 4; i++) {
                uint4 u;
                u.x = cvt_tf32(av[i].x); u.y = cvt_tf32(av[i].y); u.z = cvt_tf32(av[i].z); u.w = cvt_tf32(av[i].w);
                *(uint4*)&sA[nxt][(r0 + 32 * i) * LDR + kq] = u;
                u.x = cvt_tf32(bv[i].x); u.y = cvt_tf32(bv[i].y); u.z = cvt_tf32(bv[i].z); u.w = cvt_tf32(bv[i].w);
                *(uint4*)&sB[nxt][(r0 + 32 * i) * LDR + kq] = u;
            }
            __syncthreads();
        }
    }
}

// epilogue element mapping:
// row = bm + wm*64 + mt*16 + gid + hh*8 ; col = bn + wn*64 + nt*8 + tq*2 + e
// val = acc[mt][nt][hh*2+e]

// ---------------- mask dtype detection ----------------
__global__ void k_detect(const unsigned char* __restrict__ m) {
    __shared__ int f1, f3;
    if (threadIdx.x == 0) { f1 = 0; f3 = 0; }
    __syncthreads();
    int l1 = 0, l3 = 0;
    const uchar4* m4 = reinterpret_cast<const uchar4*>(m);
    for (int i = threadIdx.x; i < 16384; i += 256) { uchar4 c = m4[i]; l1 |= c.y; l3 |= c.w; }
    if (l1) atomicOr(&f1, 1);
    if (l3) atomicOr(&f3, 1);
    __syncthreads();
    if (threadIdx.x == 0) g_mask_flag = f1 ? 1 : (f3 ? 2 : 0);
}

// ---------------- weight transpose: g_WT[z][out][in] = W[in][out] ----------------
__global__ void k_transp(const float* __restrict__ W0, const float* __restrict__ W1,
                         const float* __restrict__ W2, const float* __restrict__ W3) {
    __shared__ float t[32][33];
    const int z = blockIdx.z;
    const float* W = (z == 0) ? W0 : (z == 1) ? W1 : (z == 2) ? W2 : W3;
    float* O = g_WT + (size_t)z * ND * ND;
    int x = blockIdx.x * 32 + threadIdx.x;
    #pragma unroll
    for (int j = 0; j < 32; j += 8)
        t[threadIdx.y + j][threadIdx.x] = W[(size_t)(blockIdx.y * 32 + threadIdx.y + j) * ND + x];
    __syncthreads();
    int ox = blockIdx.y * 32 + threadIdx.x;
    #pragma unroll
    for (int j = 0; j < 32; j += 8)
        O[(size_t)(blockIdx.x * 32 + threadIdx.y + j) * ND + ox] = t[threadIdx.x][threadIdx.y + j];
}

// ---------------- QKV projections, head-deinterleave epilogue ----------------
__global__ __launch_bounds__(128, 2) void k_qkv_t(
    const float* __restrict__ de, const float* __restrict__ en,
    const float* __restrict__ bq, const float* __restrict__ bk, const float* __restrict__ bv) {
    const int z = blockIdx.z;
    const float* X    = (z == 0) ? de : en;
    const float* bias = (z == 0) ? bq : (z == 1 ? bk : bv);
    const float* WT   = g_WT + (size_t)z * ND * ND;
    const int bm = blockIdx.y * 128, bn = blockIdx.x * 128;

    float acc[4][8][4];
    gemm_mma(X + (size_t)bm * ND, ND, WT + (size_t)bn * ND, ND, ND, acc);

    const int lane = threadIdx.x & 31, wid = threadIdx.x >> 5;
    const int m0 = (wid & 1) * 64, n0 = (wid >> 1) * 64;
    const int gid = lane >> 2, tq = lane & 3;
    float* qdst = (z == 0) ? g_Q : g_K;
    #pragma unroll
    for (int mt = 0; mt < 4; mt++)
        #pragma unroll
        for (int hh = 0; hh < 2; hh++) {
            int m = bm + m0 + mt * 16 + gid + hh * 8;
            int b = m >> 11, l = m & (NL - 1);
            #pragma unroll
            for (int nt = 0; nt < 8; nt++)
                #pragma unroll
                for (int e = 0; e < 2; e++) {
                    int n = bn + n0 + nt * 8 + tq * 2 + e;
                    float val = acc[mt][nt][hh * 2 + e] + bias[n];
                    int h = n & 7, jj = n >> 3;    // interleaved split: feature = jj*8+h
                    if (z < 2) qdst[(((size_t)(b * NH + h) * NL + l) << 7) + jj] = val;
                    else       g_V[((size_t)(b * NH + h) * NHD + jj) * NL + l] = val;  // V^T
                }
        }
}

// ---------------- S = Q K^T / 32, masked ----------------
__global__ __launch_bounds__(128, 2) void k_qk_t(const unsigned char* __restrict__ maskraw) {
    const int z = blockIdx.z, b = z >> 3;
    const int bm = blockIdx.y * 128, bn = blockIdx.x * 128;
    const float* Qb = g_Q + (size_t)z * NL * NHD;
    const float* Kb = g_K + (size_t)z * NL * NHD;

    float acc[4][8][4];
    gemm_mma(Qb + (size_t)bm * NHD, NHD, Kb + (size_t)bn * NHD, NHD, NHD, acc);

    const int lane = threadIdx.x & 31, wid = threadIdx.x >> 5;
    const int m0 = (wid & 1) * 64, n0 = (wid >> 1) * 64;
    const int gid = lane >> 2, tq = lane & 3;
    const int mf = g_mask_flag;
    #pragma unroll
    for (int mt = 0; mt < 4; mt++)
        #pragma unroll
        for (int hh = 0; hh < 2; hh++) {
            int m = bm + m0 + mt * 16 + gid + hh * 8;
            const size_t mrow = ((size_t)b * NL + m) * NL;
            float* srow = g_S + ((size_t)z * NL + m) * NL;
            #pragma unroll
            for (int nt = 0; nt < 8; nt++) {
                int n = bn + n0 + nt * 8 + tq * 2;
                float v0 = acc[mt][nt][hh * 2 + 0] * 0.03125f;   // 1/sqrt(1024)
                float v1 = acc[mt][nt][hh * 2 + 1] * 0.03125f;
                bool k0, k1;
                if (mf == 1) {
                    const unsigned char* mp = maskraw + mrow + n;
                    k0 = mp[0] != 0; k1 = mp[1] != 0;
                } else if (mf == 2) {
                    const float* mp = (const float*)maskraw + mrow + n;
                    k0 = mp[0] != 0.0f; k1 = mp[1] != 0.0f;
                } else {
                    const int* mp = (const int*)maskraw + mrow + n;
                    k0 = mp[0] != 0; k1 = mp[1] != 0;
                }
                float2 o;
                o.x = k0 ? -1e10f : v0;
                o.y = k1 ? -1e10f : v1;
                *(float2*)(srow + n) = o;
            }
        }
}

// ---------------- O = P V, concat-layout epilogue ----------------
__global__ __launch_bounds__(128, 2) void k_pv_t() {
    const int z = blockIdx.z, b = z >> 3, h = z & 7;
    const int bm = blockIdx.y * 128;
    const float* P  = g_S + (size_t)z * NL * NL + (size_t)bm * NL;
    const float* Vt = g_V + (size_t)z * NHD * NL;        // [j][l], ld = NL

    float acc[4][8][4];
    gemm_mma(P, NL, Vt, NL, NL, acc);

    const int lane = threadIdx.x & 31, wid = threadIdx.x >> 5;
    const int m0 = (wid & 1) * 64, n0 = (wid >> 1) * 64;
    const int gid = lane >> 2, tq = lane & 3;
    #pragma unroll
    for (int mt = 0; mt < 4; mt++)
        #pragma unroll
        for (int hh = 0; hh < 2; hh++) {
            int m = bm + m0 + mt * 16 + gid + hh * 8;
            float* arow = g_A + ((size_t)b * NL + m) * ND + h * NHD;
            #pragma unroll
            for (int nt = 0; nt < 8; nt++) {
                int n = n0 + nt * 8 + tq * 2;
                float2 o;
                o.x = acc[mt][nt][hh * 2 + 0];
                o.y = acc[mt][nt][hh * 2 + 1];
                *(float2*)(arow + n) = o;
            }
        }
}

// ---------------- R = A Wo + bo + de (residual) ----------------
__global__ __launch_bounds__(128, 2) void k_out_t(const float* __restrict__ bo,
                                                  const float* __restrict__ de) {
    const int bm = blockIdx.y * 128, bn = blockIdx.x * 128;
    const float* WoT = g_WT + (size_t)3 * ND * ND;

    float acc[4][8][4];
    gemm_mma(g_A + (size_t)bm * ND, ND, WoT + (size_t)bn * ND, ND, ND, acc);

    const int lane = threadIdx.x & 31, wid = threadIdx.x >> 5;
    const int m0 = (wid & 1) * 64, n0 = (wid >> 1) * 64;
    const int gid = lane >> 2, tq = lane & 3;
    #pragma unroll
    for (int mt = 0; mt < 4; mt++)
        #pragma unroll
        for (int hh = 0; hh < 2; hh++) {
            int m = bm + m0 + mt * 16 + gid + hh * 8;
            const float* drow = de + (size_t)m * ND;
            float* rrow = g_R + (size_t)m * ND;
            #pragma unroll
            for (int nt = 0; nt < 8; nt++) {
                int n = bn + n0 + nt * 8 + tq * 2;
                float2 d2 = *(const float2*)(drow + n);
                float2 b2 = *(const float2*)(bo + n);
                float2 o;
                o.x = acc[mt][nt][hh * 2 + 0] + b2.x + d2.x;
                o.y = acc[mt][nt][hh * 2 + 1] + b2.y + d2.y;
                *(float2*)(rrow + n) = o;
            }
        }
}

// ---------------- block-wide allreduce ----------------
__device__ __forceinline__ float blockAllReduce(float v, bool doMax) {
    __shared__ float sh[8];
    __shared__ float res;
    #pragma unroll
    for (int o = 16; o; o >>= 1) {
        float t = __shfl_xor_sync(0xffffffffu, v, o);
        v = doMax ? fmaxf(v, t) : (v + t);
    }
    if ((threadIdx.x & 31) == 0) sh[threadIdx.x >> 5] = v;
    __syncthreads();
    if (threadIdx.x < 32) {
        float t = (threadIdx.x < 8) ? sh[threadIdx.x] : (doMax ? -INFINITY : 0.0f);
        #pragma unroll
        for (int o = 4; o; o >>= 1) {
            float u = __shfl_xor_sync(0xffffffffu, t, o);
            t = doMax ? fmaxf(t, u) : (t + u);
        }
        if (threadIdx.x == 0) res = t;
    }
    __syncthreads();
    return res;
}

// ---------------- row softmax over S (in place) ----------------
__global__ __launch_bounds__(256) void k_softmax() {
    size_t row = blockIdx.x;
    float4* p = reinterpret_cast<float4*>(g_S) + row * (NL / 4);
    float4 a = p[threadIdx.x];
    float4 c = p[threadIdx.x + 256];
    float m = fmaxf(fmaxf(fmaxf(a.x, a.y), fmaxf(a.z, a.w)),
                    fmaxf(fmaxf(c.x, c.y), fmaxf(c.z, c.w)));
    m = blockAllReduce(m, true);
    a.x = __expf(a.x - m); a.y = __expf(a.y - m); a.z = __expf(a.z - m); a.w = __expf(a.w - m);
    c.x = __expf(c.x - m); c.y = __expf(c.y - m); c.z = __expf(c.z - m); c.w = __expf(c.w - m);
    float s = a.x + a.y + a.z + a.w + c.x + c.y + c.z + c.w;
    s = blockAllReduce(s, false);
    float inv = 1.0f / s;
    a.x *= inv; a.y *= inv; a.z *= inv; a.w *= inv;
    c.x *= inv; c.y *= inv; c.z *= inv; c.w *= inv;
    p[threadIdx.x] = a;
    p[threadIdx.x + 256] = c;
}

// ---------------- LayerNorm (ddof=1, eps=1e-8, scalar gamma/beta) ----------------
__global__ __launch_bounds__(256) void k_ln(
    float* __restrict__ out, const float* __restrict__ gamma, const float* __restrict__ beta) {
    size_t row = blockIdx.x;
    const float4* x4 = reinterpret_cast<const float4*>(g_R) + row * (ND / 4);
    float4 v = x4[threadIdx.x];
    float s  = v.x + v.y + v.z + v.w;
    float ss = v.x * v.x + v.y * v.y + v.z * v.z + v.w * v.w;
    s  = blockAllReduce(s,  false);
    ss = blockAllReduce(ss, false);
    float mu  = s * (1.0f / 1024.0f);
    float var = (ss - 1024.0f * mu * mu) * (1.0f / 1023.0f);
    float w = rsqrtf(var + 1e-8f);
    float g = gamma[0] * w, bb = beta[0];
    float4 o;
    o.x = (v.x - mu) * g + bb;
    o.y = (v.y - mu) * g + bb;
    o.z = (v.z - mu) * g + bb;
    o.w = (v.w - mu) * g + bb;
    reinterpret_cast<float4*>(out)[row * (ND / 4) + threadIdx.x] = o;
}

// ---------------- launch ----------------
extern "C" void kernel_launch(void* const* d_in, const int* in_sizes, int n_in,
                              void* d_out, int out_size) {
    (void)in_sizes; (void)n_in; (void)out_size;
    const float* en = (const float*)d_in[0];
    const float* de = (const float*)d_in[1];
    const unsigned char* mask = (const unsigned char*)d_in[2];
    const float* Wq = (const float*)d_in[3];
    const float* bq = (const float*)d_in[4];
    const float* Wk = (const float*)d_in[5];
    const float* bk = (const float*)d_in[6];
    const float* Wv = (const float*)d_in[7];
    const float* bv = (const float*)d_in[8];
    const float* Wo = (const float*)d_in[9];
    const float* bo = (const float*)d_in[10];
    const float* gamma = (const float*)d_in[11];
    const float* beta  = (const float*)d_in[12];
    float* out = (float*)d_out;

    k_detect<<<1, 256>>>(mask);
    k_transp<<<dim3(32, 32, 4), dim3(32, 8)>>>(Wq, Wk, Wv, Wo);
    k_qkv_t<<<dim3(ND / 128, (NB * NL) / 128, 3), 128>>>(de, en, bq, bk, bv);
    k_qk_t<<<dim3(NL / 128, NL / 128, NZ), 128>>>(mask);
    k_softmax<<<NZ * NL, 256>>>();
    k_pv_t<<<dim3(1, NL / 128, NZ), 128>>>();
    k_out_t<<<dim3(ND / 128, (NB * NL) / 128, 1), 128>>>(bo, de);
    k_ln<<<NB * NL, 256>>>(out, gamma, beta);
}

// round 14
// speedup vs baseline: 1.1574x; 1.0432x over previous
#include <cuda_runtime.h>
#include <math.h>
#include <stdint.h>

// Problem constants
#define NB  2
#define NL  2048
#define ND  1024
#define NH  8
#define NHD 128
#define NZ  (NB*NH)   // 16 batched heads

// ---------------- static device scratch ----------------
__device__ float g_Q[(size_t)NZ * NL * NHD];   // [z][l][j]      (tf32-rounded)
__device__ float g_K[(size_t)NZ * NL * NHD];   // [z][l][j]      (tf32-rounded)
__device__ float g_V[(size_t)NZ * NHD * NL];   // [z][j][l]      (tf32-rounded)
__device__ float g_S[(size_t)NZ * NL * NL];    // scores -> probs (probs tf32-rounded)
__device__ float g_A[(size_t)NB * NL * ND];    // concat attn out (tf32-rounded)
__device__ float g_R[(size_t)NB * NL * ND];    // pre-LN result (fp32)
__device__ float g_WT[(size_t)4 * ND * ND];    // W^T [q,k,v,o]  (tf32-rounded)
__device__ float g_DE[(size_t)NB * NL * ND];   // tf32-rounded de
__device__ float g_EN[(size_t)NB * NL * ND];   // tf32-rounded en
__device__ int   g_mask_flag;                  // 0=int32, 1=byte, 2=float32

// ---------------- tf32 / async-copy helpers (sm_80+ PTX; legal on compute_103) ----
__device__ __forceinline__ uint32_t cvt_tf32(float x) {
    uint32_t u; asm("cvt.rna.tf32.f32 %0, %1;" : "=r"(u) : "f"(x)); return u;
}
__device__ __forceinline__ float rtf(float x) { return __uint_as_float(cvt_tf32(x)); }

__device__ __forceinline__ void mma_tf32(float* d, const uint32_t* a, const uint32_t* b) {
    asm volatile(
        "mma.sync.aligned.m16n8k8.row.col.f32.tf32.tf32.f32 "
        "{%0,%1,%2,%3}, {%4,%5,%6,%7}, {%8,%9}, {%0,%1,%2,%3};"
        : "+f"(d[0]), "+f"(d[1]), "+f"(d[2]), "+f"(d[3])
        : "r"(a[0]), "r"(a[1]), "r"(a[2]), "r"(a[3]), "r"(b[0]), "r"(b[1]));
}
__device__ __forceinline__ uint32_t smem_u32(const void* p) {
    uint32_t a;
    asm("{ .reg .u64 t; cvta.to.shared.u64 t, %1; cvt.u32.u64 %0, t; }" : "=r"(a) : "l"(p));
    return a;
}
__device__ __forceinline__ void cp16(uint32_t d, const void* s) {
    asm volatile("cp.async.cg.shared.global [%0], [%1], 16;" :: "r"(d), "l"(s));
}
__device__ __forceinline__ void cp_commit() { asm volatile("cp.async.commit_group;" ::: "memory"); }
template<int N> __device__ __forceinline__ void cp_wait() {
    asm volatile("cp.async.wait_group %0;" :: "n"(N) : "memory");
}

// ---------------- shared GEMM core v3: cp.async 3-stage pipeline ----------------
// CTA tile 128x128, BK=16, 128 threads = 4 warps as 2(M) x 2(N); warp tile 64x64.
// Operands are pre-rounded tf32 in GMEM -> cp.async.cg moves them GMEM->SMEM
// bypassing L1 and the register file (no LDG/STS/cvt in the mainloop).
// Smem rows padded to LDR=20 floats: conflict-free fragment access, 80B rows
// keep 16B alignment for cp.async.
#define LDR 20
#define SM_TILE (128 * LDR)                          // floats per operand per stage
#define GEMM_SMEM (3 * 2 * SM_TILE * 4)              // 61440 bytes

__device__ __forceinline__ void gemm_mma(
    const float* __restrict__ A, int lda,
    const float* __restrict__ B, int ldb,
    int K, float acc[4][8][4])
{
    extern __shared__ float sm[];                    // [3][2][SM_TILE]
    const int tid  = threadIdx.x;
    const int lane = tid & 31, wid = tid >> 5;
    const int m0 = (wid & 1) * 64, n0 = (wid >> 1) * 64;
    const int gid = lane >> 2, tq = lane & 3;

    const int r0 = tid >> 2;                         // rows 0..31 (+32,+64,+96)
    const int kq = (tid & 3) << 2;                   // float offset in 16-wide k slab

    const uint32_t sbase = smem_u32(sm);
    uint32_t soff[4];
    #pragma unroll
    for (int i = 0; i < 4; i++) soff[i] = (uint32_t)(((r0 + 32 * i) * LDR + kq) * 4);

    #pragma unroll
    for (int mt = 0; mt < 4; mt++)
        #pragma unroll
        for (int nt = 0; nt < 8; nt++)
            #pragma unroll
            for (int r = 0; r < 4; r++) acc[mt][nt][r] = 0.0f;

    auto issue = [&](int t, int s) {
        const float* Ap = A + t * 16;
        const float* Bp = B + t * 16;
        const uint32_t sa = sbase + (uint32_t)(s * 2 * SM_TILE * 4);
        const uint32_t sb = sa + (uint32_t)(SM_TILE * 4);
        #pragma unroll
        for (int i = 0; i < 4; i++) {
            cp16(sa + soff[i], Ap + (size_t)(r0 + 32 * i) * lda + kq);
            cp16(sb + soff[i], Bp + (size_t)(r0 + 32 * i) * ldb + kq);
        }
        cp_commit();
    };

    const int T = K >> 4;
    issue(0, 0);
    issue(1, 1);

    for (int t = 0; t < T; t++) {
        if (t + 2 < T) cp_wait<1>(); else cp_wait<0>();
        __syncthreads();
        if (t + 2 < T) issue(t + 2, (t + 2) % 3);    // overwrites stage consumed at t-1

        const uint32_t* sAu = (const uint32_t*)(sm + (t % 3) * 2 * SM_TILE);
        const uint32_t* sBu = sAu + SM_TILE;

        #pragma unroll
        for (int ks = 0; ks < 16; ks += 8) {
            uint32_t af[4][4], bf[8][2];
            #pragma unroll
            for (int mt = 0; mt < 4; mt++) {
                int mr = m0 + mt * 16 + gid;
                af[mt][0] = sAu[mr * LDR + ks + tq];
                af[mt][1] = sAu[(mr + 8) * LDR + ks + tq];
                af[mt][2] = sAu[mr * LDR + ks + tq + 4];
                af[mt][3] = sAu[(mr + 8) * LDR + ks + tq + 4];
            }
            #pragma unroll
            for (int nt = 0; nt < 8; nt++) {
                int nr = n0 + nt * 8 + gid;
                bf[nt][0] = sBu[nr * LDR + ks + tq];
                bf[nt][1] = sBu[nr * LDR + ks + tq + 4];
            }
            #pragma unroll
            for (int mt = 0; mt < 4; mt++)
                #pragma unroll
                for (int nt = 0; nt < 8; nt++)
                    mma_tf32(acc[mt][nt], af[mt], bf[nt]);
        }
    }
}

// epilogue element mapping:
// row = bm + (wid&1)*64 + mt*16 + gid + hh*8 ; col = bn + (wid>>1)*64 + nt*8 + tq*2 + e
// val = acc[mt][nt][hh*2+e]

// ---------------- mask dtype detection ----------------
__global__ void k_detect(const unsigned char* __restrict__ m) {
    __shared__ int f1, f3;
    if (threadIdx.x == 0) { f1 = 0; f3 = 0; }
    __syncthreads();
    int l1 = 0, l3 = 0;
    const uchar4* m4 = reinterpret_cast<const uchar4*>(m);
    for (int i = threadIdx.x; i < 16384; i += 256) { uchar4 c = m4[i]; l1 |= c.y; l3 |= c.w; }
    if (l1) atomicOr(&f1, 1);
    if (l3) atomicOr(&f3, 1);
    __syncthreads();
    if (threadIdx.x == 0) g_mask_flag = f1 ? 1 : (f3 ? 2 : 0);
}

// ---------------- pre-round de/en to tf32 copies ----------------
__global__ void k_round(const float* __restrict__ de, const float* __restrict__ en) {
    size_t i = (size_t)blockIdx.x * blockDim.x + threadIdx.x;   // float4 index
    float4 d = ((const float4*)de)[i];
    d.x = rtf(d.x); d.y = rtf(d.y); d.z = rtf(d.z); d.w = rtf(d.w);
    ((float4*)g_DE)[i] = d;
    float4 e = ((const float4*)en)[i];
    e.x = rtf(e.x); e.y = rtf(e.y); e.z = rtf(e.z); e.w = rtf(e.w);
    ((float4*)g_EN)[i] = e;
}

// ---------------- weight transpose (tf32-rounded): g_WT[z][out][in] ----------------
__global__ void k_transp(const float* __restrict__ W0, const float* __restrict__ W1,
                         const float* __restrict__ W2, const float* __restrict__ W3) {
    __shared__ float t[32][33];
    const int z = blockIdx.z;
    const float* W = (z == 0) ? W0 : (z == 1) ? W1 : (z == 2) ? W2 : W3;
    float* O = g_WT + (size_t)z * ND * ND;
    int x = blockIdx.x * 32 + threadIdx.x;
    #pragma unroll
    for (int j = 0; j < 32; j += 8)
        t[threadIdx.y + j][threadIdx.x] = W[(size_t)(blockIdx.y * 32 + threadIdx.y + j) * ND + x];
    __syncthreads();
    int ox = blockIdx.y * 32 + threadIdx.x;
    #pragma unroll
    for (int j = 0; j < 32; j += 8)
        O[(size_t)(blockIdx.x * 32 + threadIdx.y + j) * ND + ox] = rtf(t[threadIdx.x][threadIdx.y + j]);
}

// ---------------- QKV projections, head-deinterleave epilogue ----------------
__global__ __launch_bounds__(128, 2) void k_qkv_t(
    const float* __restrict__ bq, const float* __restrict__ bk, const float* __restrict__ bv) {
    const int z = blockIdx.z;
    const float* X    = (z == 0) ? g_DE : g_EN;
    const float* bias = (z == 0) ? bq : (z == 1 ? bk : bv);
    const float* WT   = g_WT + (size_t)z * ND * ND;
    const int bm = blockIdx.y * 128, bn = blockIdx.x * 128;

    float acc[4][8][4];
    gemm_mma(X + (size_t)bm * ND, ND, WT + (size_t)bn * ND, ND, ND, acc);

    const int lane = threadIdx.x & 31, wid = threadIdx.x >> 5;
    const int m0 = (wid & 1) * 64, n0 = (wid >> 1) * 64;
    const int gid = lane >> 2, tq = lane & 3;
    float* qdst = (z == 0) ? g_Q : g_K;
    #pragma unroll
    for (int mt = 0; mt < 4; mt++)
        #pragma unroll
        for (int hh = 0; hh < 2; hh++) {
            int m = bm + m0 + mt * 16 + gid + hh * 8;
            int b = m >> 11, l = m & (NL - 1);
            #pragma unroll
            for (int nt = 0; nt < 8; nt++)
                #pragma unroll
                for (int e = 0; e < 2; e++) {
                    int n = bn + n0 + nt * 8 + tq * 2 + e;
                    float val = rtf(acc[mt][nt][hh * 2 + e] + bias[n]);   // tf32 for next GEMM
                    int h = n & 7, jj = n >> 3;    // interleaved split: feature = jj*8+h
                    if (z < 2) qdst[(((size_t)(b * NH + h) * NL + l) << 7) + jj] = val;
                    else       g_V[((size_t)(b * NH + h) * NHD + jj) * NL + l] = val;  // V^T
                }
        }
}

// ---------------- S = Q K^T / 32, masked ----------------
__global__ __launch_bounds__(128, 2) void k_qk_t(const unsigned char* __restrict__ maskraw) {
    const int z = blockIdx.z, b = z >> 3;
    const int bm = blockIdx.y * 128, bn = blockIdx.x * 128;
    const float* Qb = g_Q + (size_t)z * NL * NHD;
    const float* Kb = g_K + (size_t)z * NL * NHD;

    float acc[4][8][4];
    gemm_mma(Qb + (size_t)bm * NHD, NHD, Kb + (size_t)bn * NHD, NHD, NHD, acc);

    const int lane = threadIdx.x & 31, wid = threadIdx.x >> 5;
    const int m0 = (wid & 1) * 64, n0 = (wid >> 1) * 64;
    const int gid = lane >> 2, tq = lane & 3;
    const int mf = g_mask_flag;
    #pragma unroll
    for (int mt = 0; mt < 4; mt++)
        #pragma unroll
        for (int hh = 0; hh < 2; hh++) {
            int m = bm + m0 + mt * 16 + gid + hh * 8;
            const size_t mrow = ((size_t)b * NL + m) * NL;
            float* srow = g_S + ((size_t)z * NL + m) * NL;
            #pragma unroll
            for (int nt = 0; nt < 8; nt++) {
                int n = bn + n0 + nt * 8 + tq * 2;
                float v0 = acc[mt][nt][hh * 2 + 0] * 0.03125f;   // 1/sqrt(1024)
                float v1 = acc[mt][nt][hh * 2 + 1] * 0.03125f;
                bool k0, k1;
                if (mf == 1) {
                    const unsigned char* mp = maskraw + mrow + n;
                    k0 = mp[0] != 0; k1 = mp[1] != 0;
                } else if (mf == 2) {
                    const float* mp = (const float*)maskraw + mrow + n;
                    k0 = mp[0] != 0.0f; k1 = mp[1] != 0.0f;
                } else {
                    const int* mp = (const int*)maskraw + mrow + n;
                    k0 = mp[0] != 0; k1 = mp[1] != 0;
                }
                float2 o;
                o.x = k0 ? -1e10f : v0;
                o.y = k1 ? -1e10f : v1;
                *(float2*)(srow + n) = o;
            }
        }
}

// ---------------- O = P V, concat-layout epilogue (tf32-rounded for k_out) ------
__global__ __launch_bounds__(128, 2) void k_pv_t() {
    const int z = blockIdx.z, b = z >> 3, h = z & 7;
    const int bm = blockIdx.y * 128;
    const float* P  = g_S + (size_t)z * NL * NL + (size_t)bm * NL;
    const float* Vt = g_V + (size_t)z * NHD * NL;        // [j][l], ld = NL

    float acc[4][8][4];
    gemm_mma(P, NL, Vt, NL, NL, acc);

    const int lane = threadIdx.x & 31, wid = threadIdx.x >> 5;
    const int m0 = (wid & 1) * 64, n0 = (wid >> 1) * 64;
    const int gid = lane >> 2, tq = lane & 3;
    #pragma unroll
    for (int mt = 0; mt < 4; mt++)
        #pragma unroll
        for (int hh = 0; hh < 2; hh++) {
            int m = bm + m0 + mt * 16 + gid + hh * 8;
            float* arow = g_A + ((size_t)b * NL + m) * ND + h * NHD;
            #pragma unroll
            for (int nt = 0; nt < 8; nt++) {
                int n = n0 + nt * 8 + tq * 2;
                float2 o;
                o.x = rtf(acc[mt][nt][hh * 2 + 0]);
                o.y = rtf(acc[mt][nt][hh * 2 + 1]);
                *(float2*)(arow + n) = o;
            }
        }
}

// ---------------- R = A Wo + bo + de (residual, fp32 out) ----------------
__global__ __launch_bounds__(128, 2) void k_out_t(const float* __restrict__ bo,
                                                  const float* __restrict__ de) {
    const int bm = blockIdx.y * 128, bn = blockIdx.x * 128;
    const float* WoT = g_WT + (size_t)3 * ND * ND;

    float acc[4][8][4];
    gemm_mma(g_A + (size_t)bm * ND, ND, WoT + (size_t)bn * ND, ND, ND, acc);

    const int lane = threadIdx.x & 31, wid = threadIdx.x >> 5;
    const int m0 = (wid & 1) * 64, n0 = (wid >> 1) * 64;
    const int gid = lane >> 2, tq = lane & 3;
    #pragma unroll
    for (int mt = 0; mt < 4; mt++)
        #pragma unroll
        for (int hh = 0; hh < 2; hh++) {
            int m = bm + m0 + mt * 16 + gid + hh * 8;
            const float* drow = de + (size_t)m * ND;
            float* rrow = g_R + (size_t)m * ND;
            #pragma unroll
            for (int nt = 0; nt < 8; nt++) {
                int n = bn + n0 + nt * 8 + tq * 2;
                float2 d2 = *(const float2*)(drow + n);
                float2 b2 = *(const float2*)(bo + n);
                float2 o;
                o.x = acc[mt][nt][hh * 2 + 0] + b2.x + d2.x;
                o.y = acc[mt][nt][hh * 2 + 1] + b2.y + d2.y;
                *(float2*)(rrow + n) = o;
            }
        }
}

// ---------------- block-wide allreduce ----------------
__device__ __forceinline__ float blockAllReduce(float v, bool doMax) {
    __shared__ float sh[8];
    __shared__ float res;
    #pragma unroll
    for (int o = 16; o; o >>= 1) {
        float t = __shfl_xor_sync(0xffffffffu, v, o);
        v = doMax ? fmaxf(v, t) : (v + t);
    }
    if ((threadIdx.x & 31) == 0) sh[threadIdx.x >> 5] = v;
    __syncthreads();
    if (threadIdx.x < 32) {
        float t = (threadIdx.x < 8) ? sh[threadIdx.x] : (doMax ? -INFINITY : 0.0f);
        #pragma unroll
        for (int o = 4; o; o >>= 1) {
            float u = __shfl_xor_sync(0xffffffffu, t, o);
            t = doMax ? fmaxf(t, u) : (t + u);
        }
        if (threadIdx.x == 0) res = t;
    }
    __syncthreads();
    return res;
}

// ---------------- row softmax over S (in place; probs tf32-rounded) ----------------
__global__ __launch_bounds__(256) void k_softmax() {
    size_t row = blockIdx.x;
    float4* p = reinterpret_cast<float4*>(g_S) + row * (NL / 4);
    float4 a = p[threadIdx.x];
    float4 c = p[threadIdx.x + 256];
    float m = fmaxf(fmaxf(fmaxf(a.x, a.y), fmaxf(a.z, a.w)),
                    fmaxf(fmaxf(c.x, c.y), fmaxf(c.z, c.w)));
    m = blockAllReduce(m, true);
    a.x = __expf(a.x - m); a.y = __expf(a.y - m); a.z = __expf(a.z - m); a.w = __expf(a.w - m);
    c.x = __expf(c.x - m); c.y = __expf(c.y - m); c.z = __expf(c.z - m); c.w = __expf(c.w - m);
    float s = a.x + a.y + a.z + a.w + c.x + c.y + c.z + c.w;
    s = blockAllReduce(s, false);
    float inv = 1.0f / s;
    a.x = rtf(a.x * inv); a.y = rtf(a.y * inv); a.z = rtf(a.z * inv); a.w = rtf(a.w * inv);
    c.x = rtf(c.x * inv); c.y = rtf(c.y * inv); c.z = rtf(c.z * inv); c.w = rtf(c.w * inv);
    p[threadIdx.x] = a;
    p[threadIdx.x + 256] = c;
}

// ---------------- LayerNorm (ddof=1, eps=1e-8, scalar gamma/beta) ----------------
__global__ __launch_bounds__(256) void k_ln(
    float* __restrict__ out, const float* __restrict__ gamma, const float* __restrict__ beta) {
    size_t row = blockIdx.x;
    const float4* x4 = reinterpret_cast<const float4*>(g_R) + row * (ND / 4);
    float4 v = x4[threadIdx.x];
    float s  = v.x + v.y + v.z + v.w;
    float ss = v.x * v.x + v.y * v.y + v.z * v.z + v.w * v.w;
    s  = blockAllReduce(s,  false);
    ss = blockAllReduce(ss, false);
    float mu  = s * (1.0f / 1024.0f);
    float var = (ss - 1024.0f * mu * mu) * (1.0f / 1023.0f);
    float w = rsqrtf(var + 1e-8f);
    float g = gamma[0] * w, bb = beta[0];
    float4 o;
    o.x = (v.x - mu) * g + bb;
    o.y = (v.y - mu) * g + bb;
    o.z = (v.z - mu) * g + bb;
    o.w = (v.w - mu) * g + bb;
    reinterpret_cast<float4*>(out)[row * (ND / 4) + threadIdx.x] = o;
}

// ---------------- launch ----------------
extern "C" void kernel_launch(void* const* d_in, const int* in_sizes, int n_in,
                              void* d_out, int out_size) {
    (void)in_sizes; (void)n_in; (void)out_size;
    const float* en = (const float*)d_in[0];
    const float* de = (const float*)d_in[1];
    const unsigned char* mask = (const unsigned char*)d_in[2];
    const float* Wq = (const float*)d_in[3];
    const float* bq = (const float*)d_in[4];
    const float* Wk = (const float*)d_in[5];
    const float* bk = (const float*)d_in[6];
    const float* Wv = (const float*)d_in[7];
    const float* bv = (const float*)d_in[8];
    const float* Wo = (const float*)d_in[9];
    const float* bo = (const float*)d_in[10];
    const float* gamma = (const float*)d_in[11];
    const float* beta  = (const float*)d_in[12];
    float* out = (float*)d_out;

    static bool attr_done = false;
    if (!attr_done) {
        cudaFuncSetAttribute(k_qkv_t, cudaFuncAttributeMaxDynamicSharedMemorySize, GEMM_SMEM);
        cudaFuncSetAttribute(k_qk_t,  cudaFuncAttributeMaxDynamicSharedMemorySize, GEMM_SMEM);
        cudaFuncSetAttribute(k_pv_t,  cudaFuncAttributeMaxDynamicSharedMemorySize, GEMM_SMEM);
        cudaFuncSetAttribute(k_out_t, cudaFuncAttributeMaxDynamicSharedMemorySize, GEMM_SMEM);
        attr_done = true;
    }

    k_detect<<<1, 256>>>(mask);
    k_round<<<(NB * NL * ND / 4) / 256, 256>>>(de, en);
    k_transp<<<dim3(32, 32, 4), dim3(32, 8)>>>(Wq, Wk, Wv, Wo);
    k_qkv_t<<<dim3(ND / 128, (NB * NL) / 128, 3), 128, GEMM_SMEM>>>(bq, bk, bv);
    k_qk_t<<<dim3(NL / 128, NL / 128, NZ), 128, GEMM_SMEM>>>(mask);
    k_softmax<<<NZ * NL, 256>>>();
    k_pv_t<<<dim3(1, NL / 128, NZ), 128, GEMM_SMEM>>>();
    k_out_t<<<dim3(ND / 128, (NB * NL) / 128, 1), 128, GEMM_SMEM>>>(bo, de);
    k_ln<<<NB * NL, 256>>>(out, gamma, beta);
}